// round 1
// baseline (speedup 1.0000x reference)
#include <cuda_runtime.h>

// fid[p] = clip( (va.vb)^2 / (|va|^2 |vb|^2), 0, 1 )
// va = tanh( relu(xa @ W1 + b1) @ W2 + b2 )   (quantum circuit is unitary -> cancels)

#define KDIM 784
#define KT   56
#define NKT  14   // 784 / 56

__global__ __launch_bounds__(256)
void qcm_fused(const float* __restrict__ img_a,
               const float* __restrict__ img_b,
               const float* __restrict__ W1,
               const float* __restrict__ b1,
               const float* __restrict__ W2,
               const float* __restrict__ b2,
               float* __restrict__ out)
{
    // GEMM tiles overlaid with the post-GEMM H tile (never live simultaneously)
    __shared__ union {
        struct { float As[64 * 57]; float Bs[56 * 64]; } g;  // 28928 B
        float Hs[64 * 65];                                    // 16640 B
    } sm;
    __shared__ float W2s[64 * 16];
    __shared__ float b1s[64];
    __shared__ float b2s[16];
    __shared__ float Vs[64 * 16];
    __shared__ float ssq[64];

    const int t  = threadIdx.x;
    const int tx = t & 15;       // 16 col-groups of 4
    const int ty = t >> 4;       // 16 row-groups of 4
    const int p0 = blockIdx.x * 32;   // 32 pairs per block

    // small params
    if (t < 64) b1s[t] = b1[t];
    if (t < 16) b2s[t] = b2[t];
    #pragma unroll
    for (int i = 0; i < 4; ++i) W2s[t + i * 256] = W2[t + i * 256];

    float acc[4][4];
    #pragma unroll
    for (int i = 0; i < 4; ++i)
        #pragma unroll
        for (int j = 0; j < 4; ++j) acc[i][j] = 0.0f;

    // ---- main GEMM: rows 0..31 = img_a pairs p0..p0+31, rows 32..63 = img_b ----
    for (int kt = 0; kt < NKT; ++kt) {
        const int k0 = kt * KT;

        // load A tile: 64 rows x 56 K, 896 float4
        #pragma unroll
        for (int i = 0; i < 4; ++i) {
            int idx4 = t + i * 256;
            if (idx4 < 896) {
                int r = idx4 / 14;
                int q = idx4 - r * 14;
                const float* src = (r < 32
                        ? img_a + (size_t)(p0 + r) * KDIM
                        : img_b + (size_t)(p0 + r - 32) * KDIM) + k0 + q * 4;
                float4 v = *(const float4*)src;
                float* dst = &sm.g.As[r * 57 + q * 4];
                dst[0] = v.x; dst[1] = v.y; dst[2] = v.z; dst[3] = v.w;
            }
        }
        // load B tile: 56 K x 64 N (W1 natural layout), 896 float4
        #pragma unroll
        for (int i = 0; i < 4; ++i) {
            int idx4 = t + i * 256;
            if (idx4 < 896) {
                int kk = idx4 >> 4;
                int nq = idx4 & 15;
                *(float4*)&sm.g.Bs[kk * 64 + nq * 4] =
                    *(const float4*)(W1 + (size_t)(k0 + kk) * 64 + nq * 4);
            }
        }
        __syncthreads();

        #pragma unroll 14
        for (int kk = 0; kk < KT; ++kk) {
            float a0 = sm.g.As[(ty * 4 + 0) * 57 + kk];
            float a1 = sm.g.As[(ty * 4 + 1) * 57 + kk];
            float a2 = sm.g.As[(ty * 4 + 2) * 57 + kk];
            float a3 = sm.g.As[(ty * 4 + 3) * 57 + kk];
            float4 bv = *(const float4*)&sm.g.Bs[kk * 64 + tx * 4];
            acc[0][0] += a0 * bv.x; acc[0][1] += a0 * bv.y;
            acc[0][2] += a0 * bv.z; acc[0][3] += a0 * bv.w;
            acc[1][0] += a1 * bv.x; acc[1][1] += a1 * bv.y;
            acc[1][2] += a1 * bv.z; acc[1][3] += a1 * bv.w;
            acc[2][0] += a2 * bv.x; acc[2][1] += a2 * bv.y;
            acc[2][2] += a2 * bv.z; acc[2][3] += a2 * bv.w;
            acc[3][0] += a3 * bv.x; acc[3][1] += a3 * bv.y;
            acc[3][2] += a3 * bv.z; acc[3][3] += a3 * bv.w;
        }
        __syncthreads();
    }

    // ---- H = relu(acc + b1) into smem (overlays GEMM tiles) ----
    #pragma unroll
    for (int i = 0; i < 4; ++i) {
        int r = ty * 4 + i;
        #pragma unroll
        for (int j = 0; j < 4; ++j) {
            int n = tx * 4 + j;
            sm.Hs[r * 65 + n] = fmaxf(acc[i][j] + b1s[n], 0.0f);
        }
    }
    __syncthreads();

    // ---- v = tanh(H @ W2 + b2); 4 threads per row, 4 outputs each ----
    {
        int row = t >> 2;
        int seg = t & 3;
        float4 bb = *(const float4*)&b2s[seg * 4];
        float s0 = bb.x, s1 = bb.y, s2 = bb.z, s3 = bb.w;
        #pragma unroll 16
        for (int kk = 0; kk < 64; ++kk) {
            float  h = sm.Hs[row * 65 + kk];
            float4 w = *(const float4*)&W2s[kk * 16 + seg * 4];
            s0 += h * w.x; s1 += h * w.y; s2 += h * w.z; s3 += h * w.w;
        }
        s0 = tanhf(s0); s1 = tanhf(s1); s2 = tanhf(s2); s3 = tanhf(s3);
        float sq = s0 * s0 + s1 * s1 + s2 * s2 + s3 * s3;
        sq += __shfl_xor_sync(0xffffffffu, sq, 1);
        sq += __shfl_xor_sync(0xffffffffu, sq, 2);
        *(float4*)&Vs[row * 16 + seg * 4] = make_float4(s0, s1, s2, s3);
        if (seg == 0) ssq[row] = sq;
    }
    __syncthreads();

    // ---- fid = (va.vb)^2 / (|va|^2 |vb|^2), clipped ----
    if (t < 128) {
        int p   = t >> 2;
        int seg = t & 3;
        float4 a = *(const float4*)&Vs[p * 16 + seg * 4];
        float4 b = *(const float4*)&Vs[(p + 32) * 16 + seg * 4];
        float d = a.x * b.x + a.y * b.y + a.z * b.z + a.w * b.w;
        d += __shfl_xor_sync(0xffffffffu, d, 1);
        d += __shfl_xor_sync(0xffffffffu, d, 2);
        if (seg == 0) {
            float fid = (d * d) / (ssq[p] * ssq[p + 32]);
            out[p0 + p] = fminf(fmaxf(fid, 0.0f), 1.0f);
        }
    }
}

extern "C" void kernel_launch(void* const* d_in, const int* in_sizes, int n_in,
                              void* d_out, int out_size)
{
    const float* img_a = (const float*)d_in[0];
    const float* img_b = (const float*)d_in[1];
    const float* W1    = (const float*)d_in[2];
    const float* b1    = (const float*)d_in[3];
    const float* W2    = (const float*)d_in[4];
    const float* b2    = (const float*)d_in[5];
    // d_in[6] = theta: unused — the circuit is unitary, fidelity is invariant.
    float* out = (float*)d_out;

    int pairs  = out_size;          // 65536
    int blocks = pairs / 32;        // 32 pairs per block
    qcm_fused<<<blocks, 256>>>(img_a, img_b, W1, b1, W2, b2, out);
}